// round 4
// baseline (speedup 1.0000x reference)
#include <cuda_runtime.h>

#define B_ 4
#define N_ 4096
#define D_ 256

// 16 MB scratch for projected_val = val @ Wv  (device-global: no allocation)
static __device__ float g_projval[B_ * N_ * D_];

// ---------- packed f32x2 helpers (Blackwell FFMA2) ----------
__device__ __forceinline__ unsigned long long ffma2(unsigned long long a,
                                                    unsigned long long b,
                                                    unsigned long long c) {
    unsigned long long d;
    asm("fma.rn.f32x2 %0, %1, %2, %3;" : "=l"(d) : "l"(a), "l"(b), "l"(c));
    return d;
}
__device__ __forceinline__ unsigned long long dup2(float x) {
    unsigned long long d;
    asm("mov.b64 %0, {%1, %1};" : "=l"(d) : "f"(x));
    return d;
}
__device__ __forceinline__ float2 unpk(unsigned long long v) {
    float2 r;
    asm("mov.b64 {%0, %1}, %2;" : "=f"(r.x), "=f"(r.y) : "l"(v));
    return r;
}
union V4 {
    float4 f;
    unsigned long long u[2];
};

// =====================================================================
// Kernel 1: g_projval[row][e] = sum_d val[row][d] * Wv[d][e]
// rows = B*N = 16384 flattened. Tile 64 rows x 64 e, k-tile 32.
// 256 threads as (tx 16, ty 16), 4x4 microtile, f32x2 packed FMA.
// =====================================================================
__global__ __launch_bounds__(256, 2)
void proj_kernel(const float* __restrict__ val, const float* __restrict__ Wv) {
    __shared__ float As[64 * 36];   // [row][kk], stride 36 (16B-aligned rows)
    __shared__ float Bs[32 * 68];   // [kk][e],  stride 68 (conflict-free LDS.128)
    const int t = threadIdx.x;
    const int tx = t & 15, ty = t >> 4;
    const int row0 = blockIdx.y * 64;
    const int e0 = blockIdx.x * 64;

    unsigned long long acc[4][2] = {};
    for (int k0 = 0; k0 < D_; k0 += 32) {
#pragma unroll
        for (int p = 0; p < 2; p++) {           // A: 64x32 = 512 float4, 2/thread
            int idx = p * 256 + t;
            int r = idx >> 3, q = idx & 7;
            *(float4*)&As[r * 36 + q * 4] =
                *(const float4*)&val[(size_t)(row0 + r) * D_ + k0 + q * 4];
        }
#pragma unroll
        for (int p = 0; p < 2; p++) {           // B(Wv): 32x64, already k-major
            int idx = p * 256 + t;
            int kr = idx >> 4, ec = idx & 15;
            *(float4*)&Bs[kr * 68 + ec * 4] =
                *(const float4*)&Wv[(k0 + kr) * D_ + e0 + ec * 4];
        }
        __syncthreads();
#pragma unroll 16
        for (int kk = 0; kk < 32; kk++) {
            V4 bv; bv.f = *(float4*)&Bs[kk * 68 + tx * 4];
#pragma unroll
            for (int i = 0; i < 4; i++) {
                unsigned long long a2 = dup2(As[(ty * 4 + i) * 36 + kk]);
                acc[i][0] = ffma2(a2, bv.u[0], acc[i][0]);
                acc[i][1] = ffma2(a2, bv.u[1], acc[i][1]);
            }
        }
        __syncthreads();
    }
#pragma unroll
    for (int i = 0; i < 4; i++) {
        V4 o; o.u[0] = acc[i][0]; o.u[1] = acc[i][1];
        *(float4*)&g_projval[(size_t)(row0 + ty * 4 + i) * D_ + e0 + tx * 4] = o.f;
    }
}

// =====================================================================
// Kernel 2: fused propagation.
// Block = (b, 32 n-rows). Stream m in chunks of 64:
//   Phase A: S[32x64] = Vn @ Vm^T  (fp32, f32x2)
//   softsign -> Es (SMEM), dstate row-reduce with state chunk
//   Phase B: dval[32x256] += Es @ projval_m  (fp32, f32x2)
// 128 threads as (tx 16, ty 8): Phase A 4x4 tile, Phase B 4x(4x float4).
// =====================================================================
__global__ __launch_bounds__(128, 4)
void prop_kernel(const float* __restrict__ val, const float* __restrict__ state,
                 float* __restrict__ out) {
    __shared__ float As[32 * 36];   // Vn rows [row][kk]
    __shared__ float Bs[32 * 68];   // Vm transposed [kk][m-row 64]
    __shared__ float Es[32 * 68];   // edges [n-row 32][m 64]
    __shared__ float Ps[16 * 256];  // projval chunk [m 16][e 256]
    __shared__ float Ss[64];        // state chunk

    const int t = threadIdx.x;
    const int tx = t & 15, ty = t >> 4;   // ty 0..7
    const int b = blockIdx.y;
    const int n0 = blockIdx.x * 32;
    const float* valb = val + (size_t)b * N_ * D_;
    const float* pvb = g_projval + (size_t)b * N_ * D_;

    unsigned long long dval[4][4][2] = {};
    float ds = 0.f;

    for (int m0 = 0; m0 < N_; m0 += 64) {
        if (t < 64) Ss[t] = state[b * N_ + m0 + t];

        // ---------- Phase A: scores 32x64 over K=256 ----------
        unsigned long long accp[4][2] = {};
        for (int k0 = 0; k0 < D_; k0 += 32) {
            {   // As: 32 rows x 32 k = 256 float4, 2/thread (row-major)
                int r = t >> 3, q = t & 7;
                *(float4*)&As[r * 36 + q * 4] =
                    *(const float4*)&valb[(size_t)(n0 + r) * D_ + k0 + q * 4];
                int idx = 128 + t;
                r = idx >> 3; q = idx & 7;
                *(float4*)&As[r * 36 + q * 4] =
                    *(const float4*)&valb[(size_t)(n0 + r) * D_ + k0 + q * 4];
            }
#pragma unroll
            for (int p = 0; p < 4; p++) {  // Bs: 64x32, transpose to [kk][m]
                int idx = p * 128 + t;
                int r = idx >> 3, q = idx & 7;
                float4 v = *(const float4*)&valb[(size_t)(m0 + r) * D_ + k0 + q * 4];
                Bs[(q * 4 + 0) * 68 + r] = v.x;
                Bs[(q * 4 + 1) * 68 + r] = v.y;
                Bs[(q * 4 + 2) * 68 + r] = v.z;
                Bs[(q * 4 + 3) * 68 + r] = v.w;
            }
            __syncthreads();
#pragma unroll 16
            for (int kk = 0; kk < 32; kk++) {
                V4 bv; bv.f = *(float4*)&Bs[kk * 68 + tx * 4];
#pragma unroll
                for (int i = 0; i < 4; i++) {
                    unsigned long long a2 = dup2(As[(ty * 4 + i) * 36 + kk]);
                    accp[i][0] = ffma2(a2, bv.u[0], accp[i][0]);
                    accp[i][1] = ffma2(a2, bv.u[1], accp[i][1]);
                }
            }
            __syncthreads();
        }

        // ---------- softsign -> Es ----------
#pragma unroll
        for (int i = 0; i < 4; i++) {
            float2 lo = unpk(accp[i][0]);
            float2 hi = unpk(accp[i][1]);
            float4 e;
            e.x = lo.x / (1.f + fabsf(lo.x));
            e.y = lo.y / (1.f + fabsf(lo.y));
            e.z = hi.x / (1.f + fabsf(hi.x));
            e.w = hi.y / (1.f + fabsf(hi.y));
            *(float4*)&Es[(ty * 4 + i) * 68 + tx * 4] = e;
        }
        __syncthreads();

        // ---------- delta_state ----------
        if (t < 32) {
            float s = 0.f;
#pragma unroll
            for (int m = 0; m < 64; m++) s += Es[t * 68 + m] * Ss[m];
            ds += s;
        }

        // ---------- Phase B: dval += Es @ Pm ----------
        for (int ms = 0; ms < 64; ms += 16) {
#pragma unroll
            for (int p = 0; p < 8; p++) {  // Ps: 16x256 = 1024 float4, 8/thread
                int idx = p * 128 + t;
                int mr = idx >> 6, c = idx & 63;
                *(float4*)&Ps[mr * 256 + c * 4] =
                    *(const float4*)&pvb[(size_t)(m0 + ms + mr) * D_ + c * 4];
            }
            __syncthreads();
#pragma unroll 8
            for (int mm = 0; mm < 16; mm++) {
                unsigned long long e2[4];
#pragma unroll
                for (int i = 0; i < 4; i++)
                    e2[i] = dup2(Es[(ty * 4 + i) * 68 + ms + mm]);
#pragma unroll
                for (int q = 0; q < 4; q++) {
                    V4 pv; pv.f = *(float4*)&Ps[mm * 256 + q * 64 + tx * 4];
#pragma unroll
                    for (int i = 0; i < 4; i++) {
                        dval[i][q][0] = ffma2(e2[i], pv.u[0], dval[i][q][0]);
                        dval[i][q][1] = ffma2(e2[i], pv.u[1], dval[i][q][1]);
                    }
                }
            }
            __syncthreads();
        }
    }

    // ---------- epilogue ----------
    if (t < 32) out[b * N_ + n0 + t] = ds;
    float* dv = out + B_ * N_;
#pragma unroll
    for (int i = 0; i < 4; i++) {
#pragma unroll
        for (int q = 0; q < 4; q++) {
            V4 o; o.u[0] = dval[i][q][0]; o.u[1] = dval[i][q][1];
            *(float4*)&dv[((size_t)b * N_ + n0 + ty * 4 + i) * D_ + q * 64 + tx * 4] = o.f;
        }
    }
}

extern "C" void kernel_launch(void* const* d_in, const int* in_sizes, int n_in,
                              void* d_out, int out_size) {
    const float* val   = (const float*)d_in[0];  // [B, N, D]
    const float* state = (const float*)d_in[1];  // [B, N]
    const float* Wv    = (const float*)d_in[2];  // [D, D]
    float* out = (float*)d_out;                  // [B*N] delta_state, then [B*N*D] delta_val

    (void)in_sizes; (void)n_in; (void)out_size;

    // projval = val @ Wv
    dim3 g1(D_ / 64, (B_ * N_) / 64);
    proj_kernel<<<g1, 256>>>(val, Wv);

    // fused propagation
    dim3 g2(N_ / 32, B_);
    prop_kernel<<<g2, 128>>>(val, state, out);
}

// round 5
// speedup vs baseline: 1.0002x; 1.0002x over previous
#include <cuda_runtime.h>

#define B_ 4
#define N_ 4096
#define D_ 256

// 16 MB scratch for projected_val = val @ Wv  (device-global: no allocation)
static __device__ float g_projval[B_ * N_ * D_];

// ---------- packed f32x2 helpers (Blackwell FFMA2) ----------
__device__ __forceinline__ unsigned long long ffma2(unsigned long long a,
                                                    unsigned long long b,
                                                    unsigned long long c) {
    unsigned long long d;
    asm("fma.rn.f32x2 %0, %1, %2, %3;" : "=l"(d) : "l"(a), "l"(b), "l"(c));
    return d;
}
__device__ __forceinline__ unsigned long long dup2(float x) {
    unsigned long long d;
    asm("mov.b64 %0, {%1, %1};" : "=l"(d) : "f"(x));
    return d;
}
__device__ __forceinline__ float2 unpk(unsigned long long v) {
    float2 r;
    asm("mov.b64 {%0, %1}, %2;" : "=f"(r.x), "=f"(r.y) : "l"(v));
    return r;
}
union V4 {
    float4 f;
    unsigned long long u[2];
};

// =====================================================================
// Kernel 1: g_projval[row][e] = sum_d val[row][d] * Wv[d][e]
// rows = B*N = 16384 flattened. Tile 64 rows x 64 e, k-tile 32.
// 256 threads as (tx 16, ty 16), 4x4 microtile, f32x2 packed FMA.
// =====================================================================
__global__ __launch_bounds__(256, 2)
void proj_kernel(const float* __restrict__ val, const float* __restrict__ Wv) {
    __shared__ float As[64 * 36];   // [row][kk], stride 36 (16B-aligned rows)
    __shared__ float Bs[32 * 68];   // [kk][e],  stride 68 (conflict-free LDS.128)
    const int t = threadIdx.x;
    const int tx = t & 15, ty = t >> 4;
    const int row0 = blockIdx.y * 64;
    const int e0 = blockIdx.x * 64;

    unsigned long long acc[4][2] = {};
    for (int k0 = 0; k0 < D_; k0 += 32) {
#pragma unroll
        for (int p = 0; p < 2; p++) {           // A: 64x32 = 512 float4, 2/thread
            int idx = p * 256 + t;
            int r = idx >> 3, q = idx & 7;
            *(float4*)&As[r * 36 + q * 4] =
                *(const float4*)&val[(size_t)(row0 + r) * D_ + k0 + q * 4];
        }
#pragma unroll
        for (int p = 0; p < 2; p++) {           // B(Wv): 32x64, already k-major
            int idx = p * 256 + t;
            int kr = idx >> 4, ec = idx & 15;
            *(float4*)&Bs[kr * 68 + ec * 4] =
                *(const float4*)&Wv[(k0 + kr) * D_ + e0 + ec * 4];
        }
        __syncthreads();
#pragma unroll 16
        for (int kk = 0; kk < 32; kk++) {
            V4 bv; bv.f = *(float4*)&Bs[kk * 68 + tx * 4];
#pragma unroll
            for (int i = 0; i < 4; i++) {
                unsigned long long a2 = dup2(As[(ty * 4 + i) * 36 + kk]);
                acc[i][0] = ffma2(a2, bv.u[0], acc[i][0]);
                acc[i][1] = ffma2(a2, bv.u[1], acc[i][1]);
            }
        }
        __syncthreads();
    }
#pragma unroll
    for (int i = 0; i < 4; i++) {
        V4 o; o.u[0] = acc[i][0]; o.u[1] = acc[i][1];
        *(float4*)&g_projval[(size_t)(row0 + ty * 4 + i) * D_ + e0 + tx * 4] = o.f;
    }
}

// =====================================================================
// Kernel 2: fused propagation.
// Block = (b, 32 n-rows). Stream m in chunks of 64:
//   Phase A: S[32x64] = Vn @ Vm^T  (fp32, f32x2)
//   softsign -> Es (SMEM), dstate row-reduce with state chunk
//   Phase B: dval[32x256] += Es @ projval_m  (fp32, f32x2)
// 128 threads as (tx 16, ty 8): Phase A 4x4 tile, Phase B 4x(4x float4).
// =====================================================================
__global__ __launch_bounds__(128, 4)
void prop_kernel(const float* __restrict__ val, const float* __restrict__ state,
                 float* __restrict__ out) {
    __shared__ float As[32 * 36];   // Vn rows [row][kk]
    __shared__ float Bs[32 * 68];   // Vm transposed [kk][m-row 64]
    __shared__ float Es[32 * 68];   // edges [n-row 32][m 64]
    __shared__ float Ps[16 * 256];  // projval chunk [m 16][e 256]
    __shared__ float Ss[64];        // state chunk

    const int t = threadIdx.x;
    const int tx = t & 15, ty = t >> 4;   // ty 0..7
    const int b = blockIdx.y;
    const int n0 = blockIdx.x * 32;
    const float* valb = val + (size_t)b * N_ * D_;
    const float* pvb = g_projval + (size_t)b * N_ * D_;

    unsigned long long dval[4][4][2] = {};
    float ds = 0.f;

    for (int m0 = 0; m0 < N_; m0 += 64) {
        if (t < 64) Ss[t] = state[b * N_ + m0 + t];

        // ---------- Phase A: scores 32x64 over K=256 ----------
        unsigned long long accp[4][2] = {};
        for (int k0 = 0; k0 < D_; k0 += 32) {
            {   // As: 32 rows x 32 k = 256 float4, 2/thread (row-major)
                int r = t >> 3, q = t & 7;
                *(float4*)&As[r * 36 + q * 4] =
                    *(const float4*)&valb[(size_t)(n0 + r) * D_ + k0 + q * 4];
                int idx = 128 + t;
                r = idx >> 3; q = idx & 7;
                *(float4*)&As[r * 36 + q * 4] =
                    *(const float4*)&valb[(size_t)(n0 + r) * D_ + k0 + q * 4];
            }
#pragma unroll
            for (int p = 0; p < 4; p++) {  // Bs: 64x32, transpose to [kk][m]
                int idx = p * 128 + t;
                int r = idx >> 3, q = idx & 7;
                float4 v = *(const float4*)&valb[(size_t)(m0 + r) * D_ + k0 + q * 4];
                Bs[(q * 4 + 0) * 68 + r] = v.x;
                Bs[(q * 4 + 1) * 68 + r] = v.y;
                Bs[(q * 4 + 2) * 68 + r] = v.z;
                Bs[(q * 4 + 3) * 68 + r] = v.w;
            }
            __syncthreads();
#pragma unroll 16
            for (int kk = 0; kk < 32; kk++) {
                V4 bv; bv.f = *(float4*)&Bs[kk * 68 + tx * 4];
#pragma unroll
                for (int i = 0; i < 4; i++) {
                    unsigned long long a2 = dup2(As[(ty * 4 + i) * 36 + kk]);
                    accp[i][0] = ffma2(a2, bv.u[0], accp[i][0]);
                    accp[i][1] = ffma2(a2, bv.u[1], accp[i][1]);
                }
            }
            __syncthreads();
        }

        // ---------- softsign -> Es ----------
#pragma unroll
        for (int i = 0; i < 4; i++) {
            float2 lo = unpk(accp[i][0]);
            float2 hi = unpk(accp[i][1]);
            float4 e;
            e.x = lo.x / (1.f + fabsf(lo.x));
            e.y = lo.y / (1.f + fabsf(lo.y));
            e.z = hi.x / (1.f + fabsf(hi.x));
            e.w = hi.y / (1.f + fabsf(hi.y));
            *(float4*)&Es[(ty * 4 + i) * 68 + tx * 4] = e;
        }
        __syncthreads();

        // ---------- delta_state ----------
        if (t < 32) {
            float s = 0.f;
#pragma unroll
            for (int m = 0; m < 64; m++) s += Es[t * 68 + m] * Ss[m];
            ds += s;
        }

        // ---------- Phase B: dval += Es @ Pm ----------
        for (int ms = 0; ms < 64; ms += 16) {
#pragma unroll
            for (int p = 0; p < 8; p++) {  // Ps: 16x256 = 1024 float4, 8/thread
                int idx = p * 128 + t;
                int mr = idx >> 6, c = idx & 63;
                *(float4*)&Ps[mr * 256 + c * 4] =
                    *(const float4*)&pvb[(size_t)(m0 + ms + mr) * D_ + c * 4];
            }
            __syncthreads();
#pragma unroll 8
            for (int mm = 0; mm < 16; mm++) {
                unsigned long long e2[4];
#pragma unroll
                for (int i = 0; i < 4; i++)
                    e2[i] = dup2(Es[(ty * 4 + i) * 68 + ms + mm]);
#pragma unroll
                for (int q = 0; q < 4; q++) {
                    V4 pv; pv.f = *(float4*)&Ps[mm * 256 + q * 64 + tx * 4];
#pragma unroll
                    for (int i = 0; i < 4; i++) {
                        dval[i][q][0] = ffma2(e2[i], pv.u[0], dval[i][q][0]);
                        dval[i][q][1] = ffma2(e2[i], pv.u[1], dval[i][q][1]);
                    }
                }
            }
            __syncthreads();
        }
    }

    // ---------- epilogue ----------
    if (t < 32) out[b * N_ + n0 + t] = ds;
    float* dv = out + B_ * N_;
#pragma unroll
    for (int i = 0; i < 4; i++) {
#pragma unroll
        for (int q = 0; q < 4; q++) {
            V4 o; o.u[0] = dval[i][q][0]; o.u[1] = dval[i][q][1];
            *(float4*)&dv[((size_t)b * N_ + n0 + ty * 4 + i) * D_ + q * 64 + tx * 4] = o.f;
        }
    }
}

extern "C" void kernel_launch(void* const* d_in, const int* in_sizes, int n_in,
                              void* d_out, int out_size) {
    const float* val   = (const float*)d_in[0];  // [B, N, D]
    const float* state = (const float*)d_in[1];  // [B, N]
    const float* Wv    = (const float*)d_in[2];  // [D, D]
    float* out = (float*)d_out;                  // [B*N] delta_state, then [B*N*D] delta_val

    (void)in_sizes; (void)n_in; (void)out_size;

    // projval = val @ Wv
    dim3 g1(D_ / 64, (B_ * N_) / 64);
    proj_kernel<<<g1, 256>>>(val, Wv);

    // fused propagation
    dim3 g2(N_ / 32, B_);
    prop_kernel<<<g2, 128>>>(val, state, out);
}